// round 17
// baseline (speedup 1.0000x reference)
#include <cuda_runtime.h>
#include <math.h>

#define BATCH 8192

// sp layout constants (bank-conflict-free padded layout)
#define RS 20            // row stride in floats
#define PS 324           // plane (channel) stride
#define SS (8 * PS)      // sample stride: 2592 floats

// ---------------------------------------------------------------------------
// Scratch
// ---------------------------------------------------------------------------
__device__ __align__(16) float g_flat[BATCH * 784]; // conv2 output [B,784]
__device__ double g_part[128][8];                   // per-fc-block BN partials
__device__ float g_bnsc[8];                         // published scale/shift
__device__ unsigned g_count = 0;                    // ticket counter (epochal)
__device__ unsigned g_done = 0;                     // completed epochs

// ---------------------------------------------------------------------------
// K1: fused conv1+pool, conv2+pool. 2 samples/block, 224 threads (R7-proven,
// at the scalar-FFMA issue wall). All inner loads LDS.128; STG.128 out.
// ---------------------------------------------------------------------------
__global__ __launch_bounds__(224, 4)
void k_conv(const float* __restrict__ x,
            const float* __restrict__ w1, const float* __restrict__ b1,
            const float* __restrict__ w2, const float* __restrict__ b2) {
    __shared__ __align__(16) float sx[2][30][32];   // padded input (1920 f)
    __shared__ __align__(16) float sp[2 * SS];      // conv1 pooled out (5184 f)
    __shared__ __align__(16) float sw1p[96];        // conv1 w, [oc][12]
    __shared__ __align__(16) float sw2p[1600];      // conv2 w, [oc]*100 + [ic]*12
    __shared__ __align__(16) float sflat[2 * 784];  // output staging
    __shared__ float sb1[8], sb2[16];

    const int tid = threadIdx.x;
    const int b0 = blockIdx.x * 2;

    for (int i = tid; i < 1920; i += 224) ((float*)sx)[i] = 0.0f;
    for (int i = tid; i < 2 * SS; i += 224) sp[i] = 0.0f;
    for (int i = tid; i < 1152; i += 224) {
        int oc = i / 72, rem = i % 72, ic = rem / 9, j = rem % 9;
        sw2p[oc * 100 + ic * 12 + j] = w2[i];
    }
    if (tid < 72) sw1p[(tid / 9) * 12 + (tid % 9)] = w1[tid];
    if (tid < 8)  sb1[tid] = b1[tid];
    if (tid < 16) sb2[tid] = b2[tid];
    __syncthreads();

    for (int i = tid; i < 2 * 784; i += 224) {
        int s = i / 784, r = i % 784;
        sx[s][r / 28 + 1][r % 28 + 1] = x[(b0 + s) * 784 + r];
    }
    __syncthreads();

    // -------- conv1 (1->8) + relu + pool -> sp --------
    {
        const int oc = tid & 7;
        const int rest = tid >> 3;      // 0..27
        const int y2 = rest % 14;
        const int s = rest / 14;
        float4 wa = *(const float4*)&sw1p[oc * 12];
        float4 wb = *(const float4*)&sw1p[oc * 12 + 4];
        float4 wc = *(const float4*)&sw1p[oc * 12 + 8];
        const float w[9] = {wa.x, wa.y, wa.z, wa.w, wb.x, wb.y, wb.z, wb.w, wc.x};
        const float bias = sb1[oc];
        float* spb = &sp[s * SS + oc * PS + (y2 + 1) * RS];

        #pragma unroll
        for (int xh = 0; xh < 2; xh++) {
            const int SH = xh * 2;
            float a0[14], a1[14];
            #pragma unroll
            for (int i2 = 0; i2 < 14; i2++) { a0[i2] = bias; a1[i2] = bias; }

            #pragma unroll
            for (int r = 0; r < 4; r++) {
                float e[20];
                const float* rp = &sx[s][2 * y2 + r][xh * 12];
                #pragma unroll
                for (int q = 0; q < 5; q++) ((float4*)e)[q] = ((const float4*)rp)[q];
                if (r < 3) {
                    #pragma unroll
                    for (int xx = 0; xx < 14; xx++) {
                        float a = a0[xx];
                        a = fmaf(e[xx + SH],     w[3 * r],     a);
                        a = fmaf(e[xx + SH + 1], w[3 * r + 1], a);
                        a = fmaf(e[xx + SH + 2], w[3 * r + 2], a);
                        a0[xx] = a;
                    }
                }
                if (r >= 1) {
                    #pragma unroll
                    for (int xx = 0; xx < 14; xx++) {
                        float a = a1[xx];
                        a = fmaf(e[xx + SH],     w[3 * (r - 1)],     a);
                        a = fmaf(e[xx + SH + 1], w[3 * (r - 1) + 1], a);
                        a = fmaf(e[xx + SH + 2], w[3 * (r - 1) + 2], a);
                        a1[xx] = a;
                    }
                }
            }
            #pragma unroll
            for (int p = 0; p < 7; p++) {
                float a = fmaxf(a0[2 * p], 0.0f);
                a = fmaxf(a, fmaxf(a0[2 * p + 1], 0.0f));
                a = fmaxf(a, fmaxf(a1[2 * p], 0.0f));
                a = fmaxf(a, fmaxf(a1[2 * p + 1], 0.0f));
                spb[xh * 7 + p + 1] = a;
            }
        }
    }
    __syncthreads();

    // -------- conv2 (8->16) + relu + pool -> sflat -> g_flat --------
    {
        const int oc = tid & 15;
        const int rest = tid >> 4;     // 0..13
        const int y2 = rest % 7;
        const int s = rest / 7;
        const float bias = sb2[oc];
        float acc0[14], acc1[14];
        #pragma unroll
        for (int i2 = 0; i2 < 14; i2++) { acc0[i2] = bias; acc1[i2] = bias; }

        #pragma unroll
        for (int ic = 0; ic < 8; ic++) {
            const float* wp = &sw2p[oc * 100 + ic * 12];
            float4 wa = *(const float4*)(wp);
            float4 wb = *(const float4*)(wp + 4);
            float4 wc = *(const float4*)(wp + 8);
            const float w[9] = {wa.x, wa.y, wa.z, wa.w, wb.x, wb.y, wb.z, wb.w, wc.x};

            const float* rowp = &sp[s * SS + ic * PS + (2 * y2) * RS];
            #pragma unroll
            for (int r = 0; r < 4; r++) {
                float e[16];
                #pragma unroll
                for (int q = 0; q < 4; q++)
                    ((float4*)e)[q] = ((const float4*)(rowp + r * RS))[q];
                if (r < 3) {
                    #pragma unroll
                    for (int xx = 0; xx < 14; xx++) {
                        float a = acc0[xx];
                        a = fmaf(e[xx],     w[3 * r],     a);
                        a = fmaf(e[xx + 1], w[3 * r + 1], a);
                        a = fmaf(e[xx + 2], w[3 * r + 2], a);
                        acc0[xx] = a;
                    }
                }
                if (r >= 1) {
                    #pragma unroll
                    for (int xx = 0; xx < 14; xx++) {
                        float a = acc1[xx];
                        a = fmaf(e[xx],     w[3 * (r - 1)],     a);
                        a = fmaf(e[xx + 1], w[3 * (r - 1) + 1], a);
                        a = fmaf(e[xx + 2], w[3 * (r - 1) + 2], a);
                        acc1[xx] = a;
                    }
                }
            }
        }

        float* stg = &sflat[s * 784 + oc * 49 + y2 * 7];
        #pragma unroll
        for (int p = 0; p < 7; p++) {
            float a = fmaxf(acc0[2 * p], 0.0f);
            a = fmaxf(a, fmaxf(acc0[2 * p + 1], 0.0f));
            a = fmaxf(a, fmaxf(acc1[2 * p], 0.0f));
            a = fmaxf(a, fmaxf(acc1[2 * p + 1], 0.0f));
            stg[p] = a;
        }
    }
    __syncthreads();

    {
        float4* dst = (float4*)&g_flat[b0 * 784];
        const float4* src = (const float4*)sflat;
        for (int i = tid; i < 392; i += 224) dst[i] = src[i];
    }
}

// ---------------------------------------------------------------------------
// Quantum gate helpers
// ---------------------------------------------------------------------------
template <int STR>
__device__ __forceinline__ void rot_rx(float* sr, float* si, float c, float s) {
    #pragma unroll
    for (int k = 0; k < 16; k++) {
        if (k & STR) continue;
        int k1 = k | STR;
        float ar0 = sr[k], ai0 = si[k], ar1 = sr[k1], ai1 = si[k1];
        sr[k]  = c * ar0 + s * ai1;
        si[k]  = c * ai0 - s * ar1;
        sr[k1] = s * ai0 + c * ar1;
        si[k1] = -s * ar0 + c * ai1;
    }
}

template <int STR>
__device__ __forceinline__ void rot_ry(float* sr, float* si, float c, float s) {
    #pragma unroll
    for (int k = 0; k < 16; k++) {
        if (k & STR) continue;
        int k1 = k | STR;
        float ar0 = sr[k], ai0 = si[k], ar1 = sr[k1], ai1 = si[k1];
        sr[k]  = c * ar0 - s * ar1;
        si[k]  = c * ai0 - s * ai1;
        sr[k1] = s * ar0 + c * ar1;
        si[k1] = s * ai0 + c * ai1;
    }
}

template <int STR>
__device__ __forceinline__ void rot_rz(float* sr, float* si, float c, float s) {
    #pragma unroll
    for (int k = 0; k < 16; k++) {
        float ar = sr[k], ai = si[k];
        if (k & STR) { sr[k] = c * ar - s * ai; si[k] = c * ai + s * ar; }
        else         { sr[k] = c * ar + s * ai; si[k] = c * ai - s * ar; }
    }
}

__device__ __forceinline__ void cnot_c3_t0(float* sr, float* si) {
    #pragma unroll
    for (int k = 1; k < 8; k += 2) {
        int k1 = k | 8;
        float tr = sr[k], ti = si[k];
        sr[k] = sr[k1]; si[k] = si[k1];
        sr[k1] = tr;    si[k1] = ti;
    }
}

// ---------------------------------------------------------------------------
// K2: FC1+relu+FC2 (ping-pong GEMM) + BN stats (last-block reduction) +
// quantum sim + PauliZ measurement — all in ONE kernel. 64 samples/block,
// 128 blocks (single resident wave -> spin-wait is deadlock-free).
// ---------------------------------------------------------------------------
#define FCS 60
#define FCBUF (2 * 64 * FCS)   // one buffer: sA[64*60] | sW[64*60]
__global__ __launch_bounds__(256)
void k_fcq(const float* __restrict__ fc1_w, const float* __restrict__ fc1_b,
           const float* __restrict__ fc2_w, const float* __restrict__ fc2_b,
           const float* __restrict__ bn_g, const float* __restrict__ bn_b,
           const float* __restrict__ rl_params, float* __restrict__ out) {
    __shared__ __align__(16) float sAW[2 * FCBUF];  // ping-pong buffers
    __shared__ __align__(16) float sfeat[256];      // feat, [s][c]
    __shared__ float sw2[256];
    __shared__ double sred[256], sred2[256];
    __shared__ double spart[8];
    __shared__ float gc[23], gs[23], gsc[8];
    __shared__ unsigned sEpoch1;
    __shared__ int sLast;

    const int tid = threadIdx.x;
    const int s0 = blockIdx.x * 64;
    const int jj = tid & 31;     // output pair {jj, jj+32}
    const int ss = tid >> 5;     // sample group: samples ss*8 .. ss*8+7

    sw2[tid] = fc2_w[tid];
    if (tid < 23) {
        float t = rl_params[tid] * 0.5f;
        gc[tid] = cosf(t);
        gs[tid] = sinf(t);
    }

    // per-thread staging plan: 7 float4 per tile (1792 total = 2 x 64 x 14)
    const float* src[7];
    int dst[7];
    #pragma unroll
    for (int j = 0; j < 7; j++) {
        int i = tid + 256 * j;
        if (i < 896) {
            int r = i / 14, q = i % 14;
            src[j] = &g_flat[(s0 + r) * 784 + q * 4];
            dst[j] = r * FCS + q * 4;
        } else {
            int i2 = i - 896;
            int r = i2 / 14, q = i2 % 14;
            src[j] = &fc1_w[r * 784 + q * 4];
            dst[j] = 64 * FCS + r * FCS + q * 4;
        }
    }

    float4 pf[7];
    #pragma unroll
    for (int j = 0; j < 7; j++) { pf[j] = *(const float4*)src[j]; src[j] += 56; }

    float acc[2][8];
    #pragma unroll
    for (int u = 0; u < 8; u++) { acc[0][u] = 0.0f; acc[1][u] = 0.0f; }

    int buf = 0;
    for (int t = 0; t < 14; t++) {
        float* sb = &sAW[buf * FCBUF];
        #pragma unroll
        for (int j = 0; j < 7; j++) *(float4*)&sb[dst[j]] = pf[j];
        if (t < 13) {
            #pragma unroll
            for (int j = 0; j < 7; j++) { pf[j] = *(const float4*)src[j]; src[j] += 56; }
        }
        __syncthreads();
        const float* sA = sb;
        const float* sW = sb + 64 * FCS;
        #pragma unroll
        for (int k4 = 0; k4 < 14; k4++) {
            float4 w0 = *(const float4*)&sW[jj * FCS + k4 * 4];
            float4 w1 = *(const float4*)&sW[(jj + 32) * FCS + k4 * 4];
            #pragma unroll
            for (int u = 0; u < 8; u++) {
                float4 a = *(const float4*)&sA[(ss * 8 + u) * FCS + k4 * 4];
                float t0 = acc[0][u], t1 = acc[1][u];
                t0 = fmaf(a.x, w0.x, t0); t1 = fmaf(a.x, w1.x, t1);
                t0 = fmaf(a.y, w0.y, t0); t1 = fmaf(a.y, w1.y, t1);
                t0 = fmaf(a.z, w0.z, t0); t1 = fmaf(a.z, w1.z, t1);
                t0 = fmaf(a.w, w0.w, t0); t1 = fmaf(a.w, w1.w, t1);
                acc[0][u] = t0; acc[1][u] = t1;
            }
        }
        buf ^= 1;
    }

    __syncthreads();
    float* sh = sAW;   // reuse buffer 0: 64 samples x stride 65
    const float bj0 = fc1_b[jj], bj1 = fc1_b[jj + 32];
    #pragma unroll
    for (int u = 0; u < 8; u++) {
        sh[(ss * 8 + u) * 65 + jj]      = fmaxf(acc[0][u] + bj0, 0.0f);
        sh[(ss * 8 + u) * 65 + jj + 32] = fmaxf(acc[1][u] + bj1, 0.0f);
    }
    __syncthreads();

    // FC2 + per-block BN partial sums (deterministic tree)
    {
        const int s = tid >> 2, c = tid & 3;
        float a = fc2_b[c];
        const float* hp = &sh[s * 65];
        const float* wc = &sw2[c * 64];
        #pragma unroll
        for (int j = 0; j < 64; j++) a = fmaf(hp[j], wc[j], a);
        sfeat[tid] = a;                       // sfeat[s*4+c]
        double v = (double)a;
        sred[tid] = v;
        sred2[tid] = v * v;
    }
    __syncthreads();
    #pragma unroll
    for (int off = 128; off >= 4; off >>= 1) {
        if (tid < off) {
            sred[tid] += sred[tid + off];
            sred2[tid] += sred2[tid + off];
        }
        __syncthreads();
    }
    if (tid < 4) {
        g_part[blockIdx.x][tid] = sred[tid];
        g_part[blockIdx.x][4 + tid] = sred2[tid];
    }

    // ---- cross-block BN finalization (last-block reduction, epochal) ----
    if (tid == 0) {
        __threadfence();
        unsigned ticket = atomicAdd(&g_count, 1u);
        sEpoch1 = (ticket >> 7) + 1u;
        sLast = ((ticket & 127u) == 127u) ? 1 : 0;
    }
    __syncthreads();

    if (sLast) {
        const int w = tid >> 5, lane = tid & 31;
        double a2 = 0.0;
        #pragma unroll
        for (int j = 0; j < 4; j++) a2 += g_part[lane + 32 * j][w];
        #pragma unroll
        for (int off = 16; off > 0; off >>= 1)
            a2 += __shfl_down_sync(0xffffffff, a2, off);
        if (lane == 0) spart[w] = a2;
        __syncthreads();
        if (tid < 4) {
            double m = spart[tid] / (double)BATCH;
            double var = spart[4 + tid] / (double)BATCH - m * m;
            float scale = (float)((double)bn_g[tid] / sqrt(var + 1e-5));
            g_bnsc[tid] = scale;
            g_bnsc[4 + tid] = bn_b[tid] - (float)m * scale;
        }
        __syncthreads();
        if (tid == 0) {
            __threadfence();
            atomicAdd(&g_done, 1u);
        }
    }

    // spin until this epoch's stats are published
    if (tid == 0) {
        unsigned target = sEpoch1;
        unsigned d;
        do {
            asm volatile("ld.acquire.gpu.global.u32 %0, [%1];"
                         : "=r"(d) : "l"(&g_done));
        } while (d < target);
    }
    __syncthreads();
    if (tid < 8) gsc[tid] = g_bnsc[tid];
    __syncthreads();

    // ---- quantum sim for this block's 64 samples (threads 0..63) ----
    if (tid < 64) {
        float sr[16], si[16];
        #pragma unroll
        for (int k = 0; k < 16; k++) { sr[k] = 0.0f; si[k] = 0.0f; }
        sr[0] = 1.0f;

        float4 f4 = *(const float4*)&sfeat[tid * 4];
        {
            float f, s, c;
            f = (f4.x * gsc[0] + gsc[4]) * 0.5f; s = sinf(f); c = cosf(f);
            rot_rx<8>(sr, si, c, s);
            f = (f4.y * gsc[1] + gsc[5]) * 0.5f; s = sinf(f); c = cosf(f);
            rot_rx<4>(sr, si, c, s);
            f = (f4.z * gsc[2] + gsc[6]) * 0.5f; s = sinf(f); c = cosf(f);
            rot_rx<2>(sr, si, c, s);
            f = (f4.w * gsc[3] + gsc[7]) * 0.5f; s = sinf(f); c = cosf(f);
            rot_rx<1>(sr, si, c, s);
        }

        #pragma unroll
        for (int r = 0; r < 7; r++) {
            rot_rx<8>(sr, si, gc[3 * r],     gs[3 * r]);
            rot_ry<4>(sr, si, gc[3 * r + 1], gs[3 * r + 1]);
            rot_rz<2>(sr, si, gc[3 * r + 2], gs[3 * r + 2]);
            cnot_c3_t0(sr, si);
        }
        rot_rx<8>(sr, si, gc[21], gs[21]);
        rot_ry<4>(sr, si, gc[22], gs[22]);

        float p[16];
        #pragma unroll
        for (int k = 0; k < 16; k++) p[k] = sr[k] * sr[k] + si[k] * si[k];
        float4 o;
        {
            float a0 = 0, a1 = 0, a2 = 0, a3 = 0;
            #pragma unroll
            for (int k = 0; k < 16; k++) {
                a0 += (k & 8) ? -p[k] : p[k];
                a1 += (k & 4) ? -p[k] : p[k];
                a2 += (k & 2) ? -p[k] : p[k];
                a3 += (k & 1) ? -p[k] : p[k];
            }
            o.x = a0; o.y = a1; o.z = a2; o.w = a3;
        }
        *(float4*)&out[(s0 + tid) * 4] = o;
    }
}

// ---------------------------------------------------------------------------
// Launch (2 kernels total)
// ---------------------------------------------------------------------------
extern "C" void kernel_launch(void* const* d_in, const int* in_sizes, int n_in,
                              void* d_out, int out_size) {
    const float* x       = (const float*)d_in[0];
    const float* conv1_w = (const float*)d_in[1];
    const float* conv1_b = (const float*)d_in[2];
    const float* conv2_w = (const float*)d_in[3];
    const float* conv2_b = (const float*)d_in[4];
    const float* fc1_w   = (const float*)d_in[5];
    const float* fc1_b   = (const float*)d_in[6];
    const float* fc2_w   = (const float*)d_in[7];
    const float* fc2_b   = (const float*)d_in[8];
    const float* bn_g    = (const float*)d_in[9];
    const float* bn_b    = (const float*)d_in[10];
    const float* rl      = (const float*)d_in[11];
    float* out = (float*)d_out;

    k_conv<<<BATCH / 2, 224>>>(x, conv1_w, conv1_b, conv2_w, conv2_b);
    k_fcq<<<BATCH / 64, 256>>>(fc1_w, fc1_b, fc2_w, fc2_b, bn_g, bn_b, rl, out);
}